// round 4
// baseline (speedup 1.0000x reference)
#include <cuda_runtime.h>
#include <math.h>

// Problem constants
#define Bz 2
#define Tt 1024
#define Dd 1024
#define Hh 16
#define HDim 64
#define Ll 8
#define Vv 32000
#define MM (Bz*Tt)   // 2048 rows

// ------------------------------------------------------------------
// Scratch (static __device__ arrays; no allocations allowed)
// ------------------------------------------------------------------
__device__ float g_x  [2097152];   // [B*T, D]        8 MB
__device__ float g_h  [2097152];   // [B*T, D]        8 MB
__device__ float g_qkv[6291456];   // [B*T, 3D]      24 MB
__device__ float g_att[33554432];  // [B*H, T, T]   134 MB
__device__ float g_o  [2097152];   // [B*T, D]        8 MB
__device__ float g_ffn[8388608];   // [B*T, 4D]      32 MB

// ------------------------------------------------------------------
// Generic tiled SGEMM: C[M,N] = A[M,K] @ op(B)  (+ fused epilogues)
//   TRANSB=false: B is [K,N] (ldb = row stride)
//   TRANSB=true : B is [N,K] (ldb = row stride), computes A @ B^T
// Batched via blockIdx.z decomposed as (batch, head) with separate strides.
// MODE: 0=none, 2=bias+residual, 3=bias+gelu, 4=scale+causal mask
// ------------------------------------------------------------------
#define BMt 128
#define BNt 128
#define BKt 8
#define TMt 8
#define TNt 8

__device__ __forceinline__ float geluf(float v){
    return 0.5f * v * (1.0f + erff(v * 0.70710678118654752f));
}

template<bool TRANSB, int MODE>
__global__ void __launch_bounds__(256) gemm_kernel(
    const float* __restrict__ A, const float* __restrict__ Bm, float* __restrict__ C,
    int M, int N, int K, int lda, int ldb, int ldc,
    int Hn,
    long long sAb, long long sAh,
    long long sBb, long long sBh,
    long long sCb, long long sCh,
    const float* __restrict__ bias,
    const float* __restrict__ Res, int ldres,
    float scale)
{
    __shared__ float As[BKt][BMt];
    __shared__ float Bs[BKt][BNt];

    int bz = blockIdx.z;
    int bb = bz / Hn, hh = bz % Hn;
    A  += bb * sAb + hh * sAh;
    Bm += bb * sBb + hh * sBh;
    C  += bb * sCb + hh * sCh;

    int tid = threadIdx.x;
    int tx = tid & 15, ty = tid >> 4;
    int rowBase = blockIdx.y * BMt;
    int colBase = blockIdx.x * BNt;

    // Global-load indexing
    int aRow = tid >> 1;           // 0..127
    int aK   = (tid & 1) << 2;     // 0 or 4
    int bRow = tid >> 5;           // 0..7   (NN)
    int bCol = (tid & 31) << 2;    // 0..124 (NN)

    float acc[TMt][TNt];
#pragma unroll
    for (int i = 0; i < TMt; i++)
#pragma unroll
        for (int j = 0; j < TNt; j++) acc[i][j] = 0.0f;

    for (int k0 = 0; k0 < K; k0 += BKt) {
        // ---- load A tile (always in-bounds: M%128==0, K%8==0) ----
        float4 av = *(const float4*)(A + (long long)(rowBase + aRow) * lda + (k0 + aK));
        As[aK+0][aRow] = av.x; As[aK+1][aRow] = av.y;
        As[aK+2][aRow] = av.z; As[aK+3][aRow] = av.w;

        // ---- load B tile ----
        if (!TRANSB) {
            int n = colBase + bCol;
            float4 bv = make_float4(0.f, 0.f, 0.f, 0.f);
            if (n < N)
                bv = *(const float4*)(Bm + (long long)(k0 + bRow) * ldb + n);
            *(float4*)&Bs[bRow][bCol] = bv;
        } else {
            int nl = tid >> 1;
            int n  = colBase + nl;
            float4 bv = make_float4(0.f, 0.f, 0.f, 0.f);
            if (n < N)
                bv = *(const float4*)(Bm + (long long)n * ldb + (k0 + aK));
            Bs[aK+0][nl] = bv.x; Bs[aK+1][nl] = bv.y;
            Bs[aK+2][nl] = bv.z; Bs[aK+3][nl] = bv.w;
        }
        __syncthreads();

        // ---- compute 8x8 microtile ----
#pragma unroll
        for (int kk = 0; kk < BKt; ++kk) {
            float4 a0 = *(const float4*)&As[kk][ty * TMt];
            float4 a1 = *(const float4*)&As[kk][ty * TMt + 4];
            float4 b0 = *(const float4*)&Bs[kk][tx * TNt];
            float4 b1 = *(const float4*)&Bs[kk][tx * TNt + 4];
            float ar[8] = {a0.x, a0.y, a0.z, a0.w, a1.x, a1.y, a1.z, a1.w};
            float br[8] = {b0.x, b0.y, b0.z, b0.w, b1.x, b1.y, b1.z, b1.w};
#pragma unroll
            for (int i = 0; i < TMt; i++)
#pragma unroll
                for (int j = 0; j < TNt; j++)
                    acc[i][j] = fmaf(ar[i], br[j], acc[i][j]);
        }
        __syncthreads();
    }

    // ---- epilogue ----
#pragma unroll
    for (int i = 0; i < TMt; i++) {
        int r = rowBase + ty * TMt + i;
#pragma unroll
        for (int jj = 0; jj < TNt; jj += 4) {
            int c = colBase + tx * TNt + jj;
            if (c >= N) continue;   // N%8==0 so whole float4 is valid when c<N
            float v[4];
#pragma unroll
            for (int q = 0; q < 4; q++) v[q] = acc[i][jj + q];

            if (MODE == 2 || MODE == 3) {
#pragma unroll
                for (int q = 0; q < 4; q++) v[q] += bias[c + q];
            }
            if (MODE == 2) {
                float4 rv = *(const float4*)(Res + (long long)r * ldres + c);
                v[0] += rv.x; v[1] += rv.y; v[2] += rv.z; v[3] += rv.w;
            }
            if (MODE == 3) {
#pragma unroll
                for (int q = 0; q < 4; q++) v[q] = geluf(v[q]);
            }
            if (MODE == 4) {
#pragma unroll
                for (int q = 0; q < 4; q++)
                    v[q] = ((c + q) > r) ? -1e30f : v[q] * scale;
            }
            *(float4*)(C + (long long)r * ldc + c) = make_float4(v[0], v[1], v[2], v[3]);
        }
    }
}

// ------------------------------------------------------------------
// Embedding: x[b,t,:] = tok_emb[ids[b,t],:] + pos_emb[t,:]
// ------------------------------------------------------------------
__global__ void __launch_bounds__(256) embed_kernel(
    const int* __restrict__ ids, const float* __restrict__ tok,
    const float* __restrict__ pos, float* __restrict__ x)
{
    int bt = blockIdx.x;
    int t  = bt % Tt;
    int id = ids[bt];
    const float4* te = (const float4*)(tok + (long long)id * Dd);
    const float4* pe = (const float4*)(pos + (long long)t  * Dd);
    float4* xo = (float4*)(x + (long long)bt * Dd);
    int i = threadIdx.x;                  // 256 threads * 4 floats = 1024 = D
    float4 a = te[i], p = pe[i];
    xo[i] = make_float4(a.x + p.x, a.y + p.y, a.z + p.z, a.w + p.w);
}

// ------------------------------------------------------------------
// LayerNorm over D=1024, one block per row
// ------------------------------------------------------------------
__global__ void __launch_bounds__(256) ln_kernel(
    const float* __restrict__ x, const float* __restrict__ w,
    const float* __restrict__ b, float* __restrict__ y)
{
    int row = blockIdx.x;
    const float4* xr = (const float4*)(x + (long long)row * Dd);
    int i = threadIdx.x;
    float4 v = xr[i];
    float s  = v.x + v.y + v.z + v.w;
    float s2 = v.x * v.x + v.y * v.y + v.z * v.z + v.w * v.w;
#pragma unroll
    for (int o = 16; o > 0; o >>= 1) {
        s  += __shfl_xor_sync(0xffffffffu, s,  o);
        s2 += __shfl_xor_sync(0xffffffffu, s2, o);
    }
    __shared__ float shs[8], shs2[8];
    int wi = i >> 5, ln = i & 31;
    if (ln == 0) { shs[wi] = s; shs2[wi] = s2; }
    __syncthreads();
    float ts = 0.f, ts2 = 0.f;
#pragma unroll
    for (int k = 0; k < 8; k++) { ts += shs[k]; ts2 += shs2[k]; }
    float mean = ts * (1.0f / Dd);
    float var  = ts2 * (1.0f / Dd) - mean * mean;
    float inv  = rsqrtf(var + 1e-5f);
    float4 wv = ((const float4*)w)[i];
    float4 bv = ((const float4*)b)[i];
    float4 o4;
    o4.x = (v.x - mean) * inv * wv.x + bv.x;
    o4.y = (v.y - mean) * inv * wv.y + bv.y;
    o4.z = (v.z - mean) * inv * wv.z + bv.z;
    o4.w = (v.w - mean) * inv * wv.w + bv.w;
    ((float4*)(y + (long long)row * Dd))[i] = o4;
}

// ------------------------------------------------------------------
// Row softmax over T=1024, one block per (b,h,q) row, in place
// ------------------------------------------------------------------
__global__ void __launch_bounds__(256) softmax_kernel(float* __restrict__ att)
{
    long long row = blockIdx.x;
    float4* p = (float4*)(att + row * Tt);
    int i = threadIdx.x;
    float4 v = p[i];
    float m = fmaxf(fmaxf(v.x, v.y), fmaxf(v.z, v.w));
#pragma unroll
    for (int o = 16; o > 0; o >>= 1)
        m = fmaxf(m, __shfl_xor_sync(0xffffffffu, m, o));
    __shared__ float shm[8], shsum[8];
    int wi = i >> 5, ln = i & 31;
    if (ln == 0) shm[wi] = m;
    __syncthreads();
    float Mx = shm[0];
#pragma unroll
    for (int k = 1; k < 8; k++) Mx = fmaxf(Mx, shm[k]);
    float e0 = __expf(v.x - Mx), e1 = __expf(v.y - Mx);
    float e2 = __expf(v.z - Mx), e3 = __expf(v.w - Mx);
    float s = e0 + e1 + e2 + e3;
#pragma unroll
    for (int o = 16; o > 0; o >>= 1)
        s += __shfl_xor_sync(0xffffffffu, s, o);
    if (ln == 0) shsum[wi] = s;
    __syncthreads();
    float ts = 0.f;
#pragma unroll
    for (int k = 0; k < 8; k++) ts += shsum[k];
    float invs = 1.0f / ts;
    p[i] = make_float4(e0 * invs, e1 * invs, e2 * invs, e3 * invs);
}

// ------------------------------------------------------------------
// Host-side dispatch
// ------------------------------------------------------------------
static void run_gemm(int transB, int mode,
    const float* A, const float* B, float* C,
    int M, int N, int K, int lda, int ldb, int ldc,
    int nbz, int Hn,
    long long sAb, long long sAh, long long sBb, long long sBh,
    long long sCb, long long sCh,
    const float* bias, const float* res, int ldres, float scale)
{
    dim3 grid((N + BNt - 1) / BNt, M / BMt, nbz);
    dim3 blk(256);
#define GCALL(TB, MD) gemm_kernel<TB, MD><<<grid, blk>>>( \
    A, B, C, M, N, K, lda, ldb, ldc, Hn, sAb, sAh, sBb, sBh, sCb, sCh, \
    bias, res, ldres, scale)
    if (!transB) {
        if      (mode == 0) GCALL(false, 0);
        else if (mode == 2) GCALL(false, 2);
        else if (mode == 3) GCALL(false, 3);
    } else {
        if      (mode == 0) GCALL(true, 0);
        else if (mode == 4) GCALL(true, 4);
    }
#undef GCALL
}

extern "C" void kernel_launch(void* const* d_in, const int* in_sizes, int n_in,
                              void* d_out, int out_size)
{
    const int*   ids  = (const int*)  d_in[0];
    const float* tok  = (const float*)d_in[1];
    const float* pos  = (const float*)d_in[2];
    const float* ln1w = (const float*)d_in[3];
    const float* ln1b = (const float*)d_in[4];
    const float* qkvw = (const float*)d_in[5];
    const float* outw = (const float*)d_in[6];
    const float* outb = (const float*)d_in[7];
    const float* ln2w = (const float*)d_in[8];
    const float* ln2b = (const float*)d_in[9];
    const float* fc1w = (const float*)d_in[10];
    const float* fc1b = (const float*)d_in[11];
    const float* fc2w = (const float*)d_in[12];
    const float* fc2b = (const float*)d_in[13];
    const float* lnfw = (const float*)d_in[14];
    const float* lnfb = (const float*)d_in[15];
    float* out = (float*)d_out;

    float *x, *h, *qkv, *att, *o, *ffn;
    cudaGetSymbolAddress((void**)&x,   g_x);
    cudaGetSymbolAddress((void**)&h,   g_h);
    cudaGetSymbolAddress((void**)&qkv, g_qkv);
    cudaGetSymbolAddress((void**)&att, g_att);
    cudaGetSymbolAddress((void**)&o,   g_o);
    cudaGetSymbolAddress((void**)&ffn, g_ffn);

    embed_kernel<<<MM, 256>>>(ids, tok, pos, x);

    const float scale = 0.125f;  // 1/sqrt(64)
    const long long sQKVb = (long long)Tt * 3 * Dd;   // batch stride in qkv buf
    const long long sATTb = (long long)Hh * Tt * Tt;  // batch stride in att buf
    const long long sATTh = (long long)Tt * Tt;

    for (int l = 0; l < Ll; l++) {
        // h = LN1(x)
        ln_kernel<<<MM, 256>>>(x, ln1w + l * Dd, ln1b + l * Dd, h);
        // qkv = h @ qkv_w[l]            [2048,1024]x[1024,3072]
        run_gemm(0, 0, h, qkvw + (long long)l * Dd * 3 * Dd, qkv,
                 MM, 3 * Dd, Dd, Dd, 3 * Dd, 3 * Dd,
                 1, 1, 0, 0, 0, 0, 0, 0, nullptr, nullptr, 0, 0.f);
        // scores = scale * Q @ K^T  (+causal mask), batched over 32 (b,h)
        run_gemm(1, 4, qkv, qkv + Dd, att,
                 Tt, Tt, HDim, 3 * Dd, 3 * Dd, Tt,
                 Bz * Hh, Hh,
                 sQKVb, HDim,
                 sQKVb, HDim,
                 sATTb, sATTh,
                 nullptr, nullptr, 0, scale);
        // softmax rows
        softmax_kernel<<<Bz * Hh * Tt, 256>>>(att);
        // o = P @ V,  batched over 32
        run_gemm(0, 0, att, qkv + 2 * Dd, o,
                 Tt, HDim, Tt, Tt, 3 * Dd, Dd,
                 Bz * Hh, Hh,
                 sATTb, sATTh,
                 sQKVb, HDim,
                 (long long)Tt * Dd, HDim,
                 nullptr, nullptr, 0, 0.f);
        // x = x + o @ out_w[l] + out_b[l]
        run_gemm(0, 2, o, outw + (long long)l * Dd * Dd, x,
                 MM, Dd, Dd, Dd, Dd, Dd,
                 1, 1, 0, 0, 0, 0, 0, 0,
                 outb + l * Dd, x, Dd, 0.f);
        // h = LN2(x)
        ln_kernel<<<MM, 256>>>(x, ln2w + l * Dd, ln2b + l * Dd, h);
        // ffn = gelu(h @ fc1_w[l] + fc1_b[l])
        run_gemm(0, 3, h, fc1w + (long long)l * Dd * 4 * Dd, ffn,
                 MM, 4 * Dd, Dd, Dd, 4 * Dd, 4 * Dd,
                 1, 1, 0, 0, 0, 0, 0, 0,
                 fc1b + (long long)l * 4 * Dd, nullptr, 0, 0.f);
        // x = x + ffn @ fc2_w[l] + fc2_b[l]
        run_gemm(0, 2, ffn, fc2w + (long long)l * 4 * Dd * Dd, x,
                 MM, Dd, 4 * Dd, 4 * Dd, Dd, Dd,
                 1, 1, 0, 0, 0, 0, 0, 0,
                 fc2b + l * Dd, x, Dd, 0.f);
    }

    // final LN + tied lm_head:  out = LNf(x) @ tok_emb^T   [2048,1024]x[32000,1024]^T
    ln_kernel<<<MM, 256>>>(x, lnfw, lnfb, h);
    run_gemm(1, 0, h, tok, out,
             MM, Vv, Dd, Dd, Dd, Vv,
             1, 1, 0, 0, 0, 0, 0, 0, nullptr, nullptr, 0, 0.f);
}

// round 5
// speedup vs baseline: 2.5540x; 2.5540x over previous
#include <cuda_runtime.h>
#include <cuda_bf16.h>
#include <math.h>
#include <stdint.h>

// Problem constants
#define Bz 2
#define Tt 1024
#define Dd 1024
#define Hh 16
#define HDim 64
#define Ll 8
#define Vv 32000
#define MM (Bz*Tt)   // 2048 rows

// ------------------------------------------------------------------
// Scratch (static __device__ arrays; no allocations allowed)
// ------------------------------------------------------------------
__device__ float g_x  [2097152];   // [B*T, D]
__device__ float g_h  [2097152];   // [B*T, D]
__device__ float g_qkv[6291456];   // [B*T, 3D]
__device__ float g_att[33554432];  // [B*H, T, T]
__device__ float g_o  [2097152];   // [B*T, D]
__device__ float g_ffn[8388608];   // [B*T, 4D]

// ------------------------------------------------------------------
// PTX helpers
// ------------------------------------------------------------------
__device__ __forceinline__ void ldsm4(uint32_t& r0, uint32_t& r1, uint32_t& r2, uint32_t& r3, uint32_t addr){
    asm volatile("ldmatrix.sync.aligned.m8n8.x4.shared.b16 {%0,%1,%2,%3},[%4];\n"
                 : "=r"(r0),"=r"(r1),"=r"(r2),"=r"(r3) : "r"(addr));
}
__device__ __forceinline__ void ldsm4t(uint32_t& r0, uint32_t& r1, uint32_t& r2, uint32_t& r3, uint32_t addr){
    asm volatile("ldmatrix.sync.aligned.m8n8.x4.trans.shared.b16 {%0,%1,%2,%3},[%4];\n"
                 : "=r"(r0),"=r"(r1),"=r"(r2),"=r"(r3) : "r"(addr));
}
__device__ __forceinline__ void mma16816(float* c, uint32_t a0, uint32_t a1, uint32_t a2, uint32_t a3,
                                         uint32_t b0, uint32_t b1){
    asm volatile("mma.sync.aligned.m16n8k16.row.col.f32.bf16.bf16.f32 "
                 "{%0,%1,%2,%3},{%4,%5,%6,%7},{%8,%9},{%0,%1,%2,%3};\n"
                 : "+f"(c[0]),"+f"(c[1]),"+f"(c[2]),"+f"(c[3])
                 : "r"(a0),"r"(a1),"r"(a2),"r"(a3),"r"(b0),"r"(b1));
}

// fp32 -> (bf16 hi, bf16 lo) split, 4 elements -> two packed uint2
__device__ __forceinline__ void cvt4(float4 v, uint2& hi, uint2& lo){
    __nv_bfloat162 h01 = __floats2bfloat162_rn(v.x, v.y);
    __nv_bfloat162 h23 = __floats2bfloat162_rn(v.z, v.w);
    float2 f01 = __bfloat1622float2(h01);
    float2 f23 = __bfloat1622float2(h23);
    __nv_bfloat162 l01 = __floats2bfloat162_rn(v.x - f01.x, v.y - f01.y);
    __nv_bfloat162 l23 = __floats2bfloat162_rn(v.z - f23.x, v.w - f23.y);
    hi.x = *reinterpret_cast<unsigned*>(&h01);
    hi.y = *reinterpret_cast<unsigned*>(&h23);
    lo.x = *reinterpret_cast<unsigned*>(&l01);
    lo.y = *reinterpret_cast<unsigned*>(&l23);
}

__device__ __forceinline__ float geluf(float v){
    return 0.5f * v * (1.0f + erff(v * 0.70710678118654752f));
}

// ------------------------------------------------------------------
// Tensor-core GEMM (bf16 hi/lo 3-term split, fp32 accum).
//   C[M,N] = A[M,K] @ op(B), TRANSB: B is [N,K]; else [K,N].
// Block tile 128x128xBK16, 8 warps (2x4), warp tile 64x32.
// MODE: 0=none, 2=bias+residual, 3=bias+gelu, 4=scale+causal mask
// ------------------------------------------------------------------
#define BMt 128
#define BNt 128
#define BKt 16
#define LDA_S 24       // A smem row stride (bf16 elems), 48B: 16B-aligned rows, conflict-free
#define LDBT_S 24      // B (NT) smem [n][k]
#define LDBN_S 136     // B (NN) smem [k][n], 272B rows
#define STAGE_E 12288  // bf16 elements per stage

template<bool TRANSB, int MODE>
__global__ void __launch_bounds__(256) gemm_mma(
    const float* __restrict__ A, const float* __restrict__ Bm, float* __restrict__ C,
    int M, int N, int K, int lda, int ldb, int ldc,
    int Hn,
    long long sAb, long long sAh,
    long long sBb, long long sBh,
    long long sCb, long long sCh,
    const float* __restrict__ bias,
    const float* __restrict__ Res, int ldres,
    float scale)
{
    __shared__ __align__(16) __nv_bfloat16 sm[2 * STAGE_E];  // 48KB
    constexpr int AHI = 0, ALO = 3072, BHI = 6144;
    constexpr int BSZ = TRANSB ? 3072 : 2176;
    constexpr int BLO = BHI + BSZ;

    int tid  = threadIdx.x;
    int lane = tid & 31, wid = tid >> 5;
    int warpRow = wid >> 2, warpCol = wid & 3;
    int rowBase = blockIdx.y * BMt;
    int colBase = blockIdx.x * BNt;

    int bz = blockIdx.z;
    int bb = bz / Hn, hh = bz % Hn;
    A  += bb * sAb + hh * sAh;
    Bm += bb * sBb + hh * sBh;
    C  += bb * sCb + hh * sCh;

    float acc[4][4][4];
#pragma unroll
    for (int i = 0; i < 4; i++)
#pragma unroll
        for (int j = 0; j < 4; j++)
#pragma unroll
            for (int q = 0; q < 4; q++) acc[i][j][q] = 0.0f;

    bool skipK = (MODE == 4) && (colBase > rowBase + BMt - 1);

    if (!skipK) {
        // ---- global-load indexing (2 float4 per thread per operand) ----
        int aM[2], sA[2], sB[2];
        const float* aPtr[2];
        const float* bPtr[2];
        bool bValid[2];
        long long bAdv = TRANSB ? (long long)BKt : (long long)BKt * ldb;
#pragma unroll
        for (int j = 0; j < 2; j++) {
            int idx = tid * 2 + j;
            aM[j] = idx >> 2;
            int aK4 = (idx & 3) * 4;
            aPtr[j] = A + (long long)(rowBase + aM[j]) * lda + aK4;
            sA[j] = aM[j] * LDA_S + aK4;
            if (TRANSB) {
                int n = idx >> 2, k4 = (idx & 3) * 4;
                bValid[j] = (colBase + n) < N;
                bPtr[j] = Bm + (long long)(colBase + n) * ldb + k4;
                sB[j] = n * LDBT_S + k4;
            } else {
                int k = idx >> 5, n4 = (idx & 31) * 4;
                bValid[j] = (colBase + n4) < N;
                bPtr[j] = Bm + (long long)k * ldb + colBase + n4;
                sB[j] = k * LDBN_S + n4;
            }
        }

        // ---- ldmatrix element offsets (per thread) ----
        int eA = (warpRow * 64 + (lane & 15)) * LDA_S + (((lane >> 4) & 1) << 3);
        int eB;
        if (TRANSB)
            eB = (warpCol * 32 + (lane & 7) + (((lane >> 4) & 1) << 3)) * LDBT_S + (lane & 8);
        else
            eB = (lane & 15) * LDBN_S + warpCol * 32 + ((lane & 16) ? 8 : 0);
        const int eBd = TRANSB ? 16 * LDBT_S : 16;  // per ntile-pair delta

        uint32_t sb = (uint32_t)__cvta_generic_to_shared(sm);

        float4 rA[2], rB[2];
        auto LOADG = [&](){
#pragma unroll
            for (int j = 0; j < 2; j++) {
                rA[j] = *(const float4*)aPtr[j];  aPtr[j] += BKt;
                rB[j] = bValid[j] ? *(const float4*)bPtr[j] : make_float4(0.f,0.f,0.f,0.f);
                bPtr[j] += bAdv;
            }
        };
        auto STORE = [&](int st){
            __nv_bfloat16* s = sm + st * STAGE_E;
#pragma unroll
            for (int j = 0; j < 2; j++) {
                uint2 hi, lo;
                cvt4(rA[j], hi, lo);
                *(uint2*)(s + AHI + sA[j]) = hi;
                *(uint2*)(s + ALO + sA[j]) = lo;
                cvt4(rB[j], hi, lo);
                *(uint2*)(s + BHI + sB[j]) = hi;
                *(uint2*)(s + BLO + sB[j]) = lo;
            }
        };

        LOADG();
        STORE(0);
        __syncthreads();

        int NK = K >> 4;
        for (int it = 0; it < NK; ++it) {
            int cur = it & 1;
            bool more = (it + 1 < NK);
            if (more) LOADG();

            // ---- load fragments + 3-term mma ----
            uint32_t base = sb + cur * (STAGE_E * 2);
            uint32_t Ah[4][4], Al[4][4], Bh[4][2], Bl[4][2];
#pragma unroll
            for (int mi = 0; mi < 4; mi++) {
                ldsm4(Ah[mi][0],Ah[mi][1],Ah[mi][2],Ah[mi][3], base + 2*(AHI + eA + mi*16*LDA_S));
                ldsm4(Al[mi][0],Al[mi][1],Al[mi][2],Al[mi][3], base + 2*(ALO + eA + mi*16*LDA_S));
            }
#pragma unroll
            for (int p = 0; p < 2; p++) {
                uint32_t r0,r1,r2,r3;
                if (TRANSB) ldsm4 (r0,r1,r2,r3, base + 2*(BHI + eB + p*eBd));
                else        ldsm4t(r0,r1,r2,r3, base + 2*(BHI + eB + p*eBd));
                Bh[2*p][0]=r0; Bh[2*p][1]=r1; Bh[2*p+1][0]=r2; Bh[2*p+1][1]=r3;
                if (TRANSB) ldsm4 (r0,r1,r2,r3, base + 2*(BLO + eB + p*eBd));
                else        ldsm4t(r0,r1,r2,r3, base + 2*(BLO + eB + p*eBd));
                Bl[2*p][0]=r0; Bl[2*p][1]=r1; Bl[2*p+1][0]=r2; Bl[2*p+1][1]=r3;
            }
#pragma unroll
            for (int mi = 0; mi < 4; mi++)
#pragma unroll
                for (int ni = 0; ni < 4; ni++) {
                    float* c = acc[mi][ni];
                    mma16816(c, Ah[mi][0],Ah[mi][1],Ah[mi][2],Ah[mi][3], Bh[ni][0],Bh[ni][1]);
                    mma16816(c, Ah[mi][0],Ah[mi][1],Ah[mi][2],Ah[mi][3], Bl[ni][0],Bl[ni][1]);
                    mma16816(c, Al[mi][0],Al[mi][1],Al[mi][2],Al[mi][3], Bh[ni][0],Bh[ni][1]);
                }

            if (more) STORE(cur ^ 1);
            __syncthreads();
        }
    }

    // ---- epilogue ----
    int wr = warpRow * 64, wc = warpCol * 32;
    int lg = lane >> 2, lc = (lane & 3) * 2;
#pragma unroll
    for (int mi = 0; mi < 4; mi++) {
        int r0 = rowBase + wr + mi * 16 + lg;
        int r1 = r0 + 8;
#pragma unroll
        for (int ni = 0; ni < 4; ni++) {
            int c = colBase + wc + ni * 8 + lc;
            if (c >= N) continue;
            float v0x = acc[mi][ni][0], v0y = acc[mi][ni][1];
            float v1x = acc[mi][ni][2], v1y = acc[mi][ni][3];
            if (MODE == 2 || MODE == 3) {
                float2 bb2 = *(const float2*)&bias[c];
                v0x += bb2.x; v0y += bb2.y; v1x += bb2.x; v1y += bb2.y;
            }
            if (MODE == 2) {
                float2 q0 = *(const float2*)(Res + (long long)r0 * ldres + c);
                float2 q1 = *(const float2*)(Res + (long long)r1 * ldres + c);
                v0x += q0.x; v0y += q0.y; v1x += q1.x; v1y += q1.y;
            }
            if (MODE == 3) {
                v0x = geluf(v0x); v0y = geluf(v0y); v1x = geluf(v1x); v1y = geluf(v1y);
            }
            if (MODE == 4) {
                v0x = (c     > r0) ? -1e30f : v0x * scale;
                v0y = (c + 1 > r0) ? -1e30f : v0y * scale;
                v1x = (c     > r1) ? -1e30f : v1x * scale;
                v1y = (c + 1 > r1) ? -1e30f : v1y * scale;
            }
            *(float2*)(C + (long long)r0 * ldc + c) = make_float2(v0x, v0y);
            *(float2*)(C + (long long)r1 * ldc + c) = make_float2(v1x, v1y);
        }
    }
}

// ------------------------------------------------------------------
// Embedding: x[b,t,:] = tok_emb[ids[b,t],:] + pos_emb[t,:]
// ------------------------------------------------------------------
__global__ void __launch_bounds__(256) embed_kernel(
    const int* __restrict__ ids, const float* __restrict__ tok,
    const float* __restrict__ pos, float* __restrict__ x)
{
    int bt = blockIdx.x;
    int t  = bt % Tt;
    int id = ids[bt];
    const float4* te = (const float4*)(tok + (long long)id * Dd);
    const float4* pe = (const float4*)(pos + (long long)t  * Dd);
    float4* xo = (float4*)(x + (long long)bt * Dd);
    int i = threadIdx.x;
    float4 a = te[i], p = pe[i];
    xo[i] = make_float4(a.x + p.x, a.y + p.y, a.z + p.z, a.w + p.w);
}

// ------------------------------------------------------------------
// LayerNorm over D=1024, one block per row
// ------------------------------------------------------------------
__global__ void __launch_bounds__(256) ln_kernel(
    const float* __restrict__ x, const float* __restrict__ w,
    const float* __restrict__ b, float* __restrict__ y)
{
    int row = blockIdx.x;
    const float4* xr = (const float4*)(x + (long long)row * Dd);
    int i = threadIdx.x;
    float4 v = xr[i];
    float s  = v.x + v.y + v.z + v.w;
    float s2 = v.x * v.x + v.y * v.y + v.z * v.z + v.w * v.w;
#pragma unroll
    for (int o = 16; o > 0; o >>= 1) {
        s  += __shfl_xor_sync(0xffffffffu, s,  o);
        s2 += __shfl_xor_sync(0xffffffffu, s2, o);
    }
    __shared__ float shs[8], shs2[8];
    int wi = i >> 5, ln = i & 31;
    if (ln == 0) { shs[wi] = s; shs2[wi] = s2; }
    __syncthreads();
    float ts = 0.f, ts2 = 0.f;
#pragma unroll
    for (int k = 0; k < 8; k++) { ts += shs[k]; ts2 += shs2[k]; }
    float mean = ts * (1.0f / Dd);
    float var  = ts2 * (1.0f / Dd) - mean * mean;
    float inv  = rsqrtf(var + 1e-5f);
    float4 wv = ((const float4*)w)[i];
    float4 bv = ((const float4*)b)[i];
    float4 o4;
    o4.x = (v.x - mean) * inv * wv.x + bv.x;
    o4.y = (v.y - mean) * inv * wv.y + bv.y;
    o4.z = (v.z - mean) * inv * wv.z + bv.z;
    o4.w = (v.w - mean) * inv * wv.w + bv.w;
    ((float4*)(y + (long long)row * Dd))[i] = o4;
}

// ------------------------------------------------------------------
// Row softmax over T=1024, one block per (b,h,q) row, in place
// ------------------------------------------------------------------
__global__ void __launch_bounds__(256) softmax_kernel(float* __restrict__ att)
{
    long long row = blockIdx.x;
    float4* p = (float4*)(att + row * Tt);
    int i = threadIdx.x;
    float4 v = p[i];
    float m = fmaxf(fmaxf(v.x, v.y), fmaxf(v.z, v.w));
#pragma unroll
    for (int o = 16; o > 0; o >>= 1)
        m = fmaxf(m, __shfl_xor_sync(0xffffffffu, m, o));
    __shared__ float shm[8], shsum[8];
    int wi = i >> 5, ln = i & 31;
    if (ln == 0) shm[wi] = m;
    __syncthreads();
    float Mx = shm[0];
#pragma unroll
    for (int k = 1; k < 8; k++) Mx = fmaxf(Mx, shm[k]);
    float e0 = __expf(v.x - Mx), e1 = __expf(v.y - Mx);
    float e2 = __expf(v.z - Mx), e3 = __expf(v.w - Mx);
    float s = e0 + e1 + e2 + e3;
#pragma unroll
    for (int o = 16; o > 0; o >>= 1)
        s += __shfl_xor_sync(0xffffffffu, s, o);
    if (ln == 0) shsum[wi] = s;
    __syncthreads();
    float ts = 0.f;
#pragma unroll
    for (int k = 0; k < 8; k++) ts += shsum[k];
    float invs = 1.0f / ts;
    p[i] = make_float4(e0 * invs, e1 * invs, e2 * invs, e3 * invs);
}

// ------------------------------------------------------------------
// Host-side dispatch
// ------------------------------------------------------------------
static void run_gemm(int transB, int mode,
    const float* A, const float* B, float* C,
    int M, int N, int K, int lda, int ldb, int ldc,
    int nbz, int Hn,
    long long sAb, long long sAh, long long sBb, long long sBh,
    long long sCb, long long sCh,
    const float* bias, const float* res, int ldres, float scale)
{
    dim3 grid((N + BNt - 1) / BNt, M / BMt, nbz);
    dim3 blk(256);
#define GCALL(TB, MD) gemm_mma<TB, MD><<<grid, blk>>>( \
    A, B, C, M, N, K, lda, ldb, ldc, Hn, sAb, sAh, sBb, sBh, sCb, sCh, \
    bias, res, ldres, scale)
    if (!transB) {
        if      (mode == 0) GCALL(false, 0);
        else if (mode == 2) GCALL(false, 2);
        else if (mode == 3) GCALL(false, 3);
    } else {
        if      (mode == 0) GCALL(true, 0);
        else if (mode == 4) GCALL(true, 4);
    }
#undef GCALL
}

extern "C" void kernel_launch(void* const* d_in, const int* in_sizes, int n_in,
                              void* d_out, int out_size)
{
    const int*   ids  = (const int*)  d_in[0];
    const float* tok  = (const float*)d_in[1];
    const float* pos  = (const float*)d_in[2];
    const float* ln1w = (const float*)d_in[3];
    const float* ln1b = (const float*)d_in[4];
    const float* qkvw = (const float*)d_in[5];
    const float* outw = (const float*)d_in[6];
    const float* outb = (const float*)d_in[7];
    const float* ln2w = (const float*)d_in[8];
    const float* ln2b = (const float*)d_in[9];
    const float* fc1w = (const float*)d_in[10];
    const float* fc1b = (const float*)d_in[11];
    const float* fc2w = (const float*)d_in[12];
    const float* fc2b = (const float*)d_in[13];
    const float* lnfw = (const float*)d_in[14];
    const float* lnfb = (const float*)d_in[15];
    float* out = (float*)d_out;

    float *x, *h, *qkv, *att, *o, *ffn;
    cudaGetSymbolAddress((void**)&x,   g_x);
    cudaGetSymbolAddress((void**)&h,   g_h);
    cudaGetSymbolAddress((void**)&qkv, g_qkv);
    cudaGetSymbolAddress((void**)&att, g_att);
    cudaGetSymbolAddress((void**)&o,   g_o);
    cudaGetSymbolAddress((void**)&ffn, g_ffn);

    embed_kernel<<<MM, 256>>>(ids, tok, pos, x);

    const float scale = 0.125f;  // 1/sqrt(64)
    const long long sQKVb = (long long)Tt * 3 * Dd;
    const long long sATTb = (long long)Hh * Tt * Tt;
    const long long sATTh = (long long)Tt * Tt;

    for (int l = 0; l < Ll; l++) {
        // h = LN1(x)
        ln_kernel<<<MM, 256>>>(x, ln1w + l * Dd, ln1b + l * Dd, h);
        // qkv = h @ qkv_w[l]
        run_gemm(0, 0, h, qkvw + (long long)l * Dd * 3 * Dd, qkv,
                 MM, 3 * Dd, Dd, Dd, 3 * Dd, 3 * Dd,
                 1, 1, 0, 0, 0, 0, 0, 0, nullptr, nullptr, 0, 0.f);
        // scores = scale * Q @ K^T (+causal), batched over (b,h)
        run_gemm(1, 4, qkv, qkv + Dd, att,
                 Tt, Tt, HDim, 3 * Dd, 3 * Dd, Tt,
                 Bz * Hh, Hh,
                 sQKVb, HDim,
                 sQKVb, HDim,
                 sATTb, sATTh,
                 nullptr, nullptr, 0, scale);
        // softmax rows
        softmax_kernel<<<Bz * Hh * Tt, 256>>>(att);
        // o = P @ V, batched
        run_gemm(0, 0, att, qkv + 2 * Dd, o,
                 Tt, HDim, Tt, Tt, 3 * Dd, Dd,
                 Bz * Hh, Hh,
                 sATTb, sATTh,
                 sQKVb, HDim,
                 (long long)Tt * Dd, HDim,
                 nullptr, nullptr, 0, 0.f);
        // x = x + o @ out_w[l] + out_b[l]
        run_gemm(0, 2, o, outw + (long long)l * Dd * Dd, x,
                 MM, Dd, Dd, Dd, Dd, Dd,
                 1, 1, 0, 0, 0, 0, 0, 0,
                 outb + l * Dd, x, Dd, 0.f);
        // h = LN2(x)
        ln_kernel<<<MM, 256>>>(x, ln2w + l * Dd, ln2b + l * Dd, h);
        // ffn = gelu(h @ fc1_w[l] + fc1_b[l])
        run_gemm(0, 3, h, fc1w + (long long)l * Dd * 4 * Dd, ffn,
                 MM, 4 * Dd, Dd, Dd, 4 * Dd, 4 * Dd,
                 1, 1, 0, 0, 0, 0, 0, 0,
                 fc1b + (long long)l * 4 * Dd, nullptr, 0, 0.f);
        // x = x + ffn @ fc2_w[l] + fc2_b[l]
        run_gemm(0, 2, ffn, fc2w + (long long)l * 4 * Dd * Dd, x,
                 MM, Dd, 4 * Dd, 4 * Dd, Dd, Dd,
                 1, 1, 0, 0, 0, 0, 0, 0,
                 fc2b + l * Dd, x, Dd, 0.f);
    }

    // final LN + tied lm_head
    ln_kernel<<<MM, 256>>>(x, lnfw, lnfb, h);
    run_gemm(1, 0, h, tok, out,
             MM, Vv, Dd, Dd, Dd, Vv,
             1, 1, 0, 0, 0, 0, 0, 0, nullptr, nullptr, 0, 0.f);
}